// round 14
// baseline (speedup 1.0000x reference)
#include <cuda_runtime.h>
#include <cstdint>

#define BATCH 2
#define S_LEN 2048
#define NU 1024
#define NH 16
#define DK 64
#define MROWS (BATCH * S_LEN)

// Scratch. Producers store tf32-pre-rounded values (Q pre-scaled by
// 1/sqrt(Dk)*log2e), so consumers load mma fragments with zero cvt.
__device__ float g_q[BATCH * NH * S_LEN * DK];
__device__ float g_k[BATCH * NH * S_LEN * DK];
__device__ float g_v[BATCH * NH * S_LEN * DK];
__device__ float g_attn[BATCH * S_LEN * NU];
// tf32-pre-rounded copies of harness inputs (bit-identical to per-load cvt).
__device__ float g_xq[MROWS * NU];
__device__ float g_xk[MROWS * NU];
__device__ float g_xv[MROWS * NU];
__device__ float g_wq[NU * NU];
__device__ float g_wk[NU * NU];
__device__ float g_wv[NU * NU];
__device__ float g_wo[NU * NU];

#define QSCALE_F (0.125f * 1.44269504088896f)   // 1/sqrt(Dk) * log2(e)

// ───────────────────────── helpers ─────────────────────────
__device__ __forceinline__ uint32_t smem_to_u32(const void* p) {
    uint32_t a;
    asm("{ .reg .u64 t; cvta.to.shared.u64 t, %1; cvt.u32.u64 %0, t; }"
        : "=r"(a) : "l"(p));
    return a;
}
__device__ __forceinline__ void cp_async16(uint32_t dst, const void* src) {
    asm volatile("cp.async.cg.shared.global [%0], [%1], 16;" :: "r"(dst), "l"(src) : "memory");
}
#define CP_ASYNC_COMMIT() asm volatile("cp.async.commit_group;" ::: "memory")
#define CP_ASYNC_WAIT(n)  asm volatile("cp.async.wait_group %0;" :: "n"(n) : "memory")

__device__ __forceinline__ uint32_t f2tf(float f) {
    uint32_t u;
    asm("cvt.rna.tf32.f32 %0, %1;" : "=r"(u) : "f"(f));
    return u;
}
__device__ __forceinline__ float fast_exp2(float x) {
    float y;
    asm("ex2.approx.f32 %0, %1;" : "=f"(y) : "f"(x));
    return y;
}
__device__ __forceinline__ void mma_tf32(float* c, const uint32_t* a, const uint32_t* b) {
    asm volatile(
        "mma.sync.aligned.m16n8k8.row.col.f32.tf32.tf32.f32 "
        "{%0,%1,%2,%3}, {%4,%5,%6,%7}, {%8,%9}, {%0,%1,%2,%3};"
        : "+f"(c[0]), "+f"(c[1]), "+f"(c[2]), "+f"(c[3])
        : "r"(a[0]), "r"(a[1]), "r"(a[2]), "r"(a[3]), "r"(b[0]), "r"(b[1]));
}
// ldmatrix x4: each 8x8 b16 matrix == 8 rows x 4 tf32; lane gets [lane>>2][lane&3]
// which is exactly the tf32 mma fragment layout.
__device__ __forceinline__ void ldsm_x4(uint32_t* r, uint32_t addr) {
    asm volatile("ldmatrix.sync.aligned.m8n8.x4.shared.b16 {%0,%1,%2,%3}, [%4];"
        : "=r"(r[0]), "=r"(r[1]), "=r"(r[2]), "=r"(r[3]) : "r"(addr));
}

// ─────────── input pre-round: fp32 -> tf32 bits (rna) ───────────
__global__ __launch_bounds__(256) void preround_kernel(
    const float* __restrict__ x0, const float* __restrict__ x1,
    const float* __restrict__ x2,
    const float* __restrict__ w0, const float* __restrict__ w1,
    const float* __restrict__ w2, const float* __restrict__ w3,
    float* __restrict__ ox0, float* __restrict__ ox1, float* __restrict__ ox2,
    float* __restrict__ ow0, float* __restrict__ ow1, float* __restrict__ ow2,
    float* __restrict__ ow3) {
    const int z = blockIdx.z;
    const float* in;
    float* out;
    int n4;
    switch (z) {
        case 0: in = x0; out = ox0; n4 = MROWS * NU / 4; break;
        case 1: in = x1; out = ox1; n4 = MROWS * NU / 4; break;
        case 2: in = x2; out = ox2; n4 = MROWS * NU / 4; break;
        case 3: in = w0; out = ow0; n4 = NU * NU / 4; break;
        case 4: in = w1; out = ow1; n4 = NU * NU / 4; break;
        case 5: in = w2; out = ow2; n4 = NU * NU / 4; break;
        default: in = w3; out = ow3; n4 = NU * NU / 4; break;
    }
    for (int i = blockIdx.x * 256 + threadIdx.x; i < n4; i += gridDim.x * 256) {
        float4 v = ((const float4*)in)[i];
        v.x = __uint_as_float(f2tf(v.x));
        v.y = __uint_as_float(f2tf(v.y));
        v.z = __uint_as_float(f2tf(v.z));
        v.w = __uint_as_float(f2tf(v.w));
        ((float4*)out)[i] = v;
    }
}

// ───────────────── tf32 mma.sync GEMM ─────────────────
// All operands pre-rounded tf32 bits; fragments loaded via ldmatrix.
#define BK 32
#define TILE_F (128 * BK)
#define TILE_BYTES (TILE_F * 4)
#define STAGE_BYTES (2 * TILE_BYTES)
#define NSTAGE 3
#define GEMM_SMEM (NSTAGE * STAGE_BYTES)

template <bool SPLIT>
__device__ __forceinline__ void gemm_body(
    const float* __restrict__ X, const float* __restrict__ W,
    const float* __restrict__ bias, float* __restrict__ C,
    char* smem, int m0, int n0, float outScale) {
    const uint32_t sb = smem_to_u32(smem);
    const int t = threadIdx.x;
    const int lane = t & 31, warp = t >> 5;
    const int mw = warp & 1, nw = warp >> 1;
    const int lr = lane >> 2, lc = lane & 3;

    const float* gA = X + (size_t)m0 * NU;
    const float* gB = W + (size_t)n0 * NU;

    auto load_tiles = [&](int st, int kt) {
#pragma unroll
        for (int i = 0; i < 8; i++) {
            int j = i * 256 + t;
            int mat = j >> 10;
            int idx = j & 1023;
            int r = idx >> 3, c16 = idx & 7;
            const float* g = (mat ? gB : gA) + (size_t)r * NU + kt * BK + c16 * 4;
            uint32_t off = (uint32_t)(r * 128 + ((c16 * 16) ^ ((r & 7) << 4)));
            cp_async16(sb + st * STAGE_BYTES + mat * TILE_BYTES + off, g);
        }
        CP_ASYNC_COMMIT();
    };

    // ldmatrix lane geometry
    const int g = lane >> 3, li = lane & 7;
    const int arow = mw * 64 + ((g & 1) << 3) + li;   // row for mt=0 (m0,m1 rows / m2,m3 cols+4)
    const int acoff = (g >> 1) << 2;
    const uint32_t aswz = (uint32_t)((arow & 7) << 2);
    const int brow = nw * 32 + ((g >> 1) << 3) + li;  // row for nt-pair p=0
    const int bcoff = (g & 1) << 2;
    const uint32_t bswz = (uint32_t)((brow & 7) << 2);

    float acc[4][4][4] = {};

    const int NKT = NU / BK;                 // 32
    load_tiles(0, 0);
    load_tiles(1, 1);
    int st = 0;
    for (int kt = 0; kt < NKT; kt++) {
        if (kt + 2 < NKT) { load_tiles((st + 2) % NSTAGE, kt + 2); CP_ASYNC_WAIT(2); }
        else if (kt + 1 < NKT) { CP_ASYNC_WAIT(1); }
        else { CP_ASYNC_WAIT(0); }
        __syncthreads();

        const uint32_t sA = sb + st * STAGE_BYTES;
        const uint32_t sB = sA + TILE_BYTES;
#pragma unroll
        for (int kk = 0; kk < BK; kk += 8) {
            uint32_t af[4][4], bf[4][2];
#pragma unroll
            for (int mt = 0; mt < 4; mt++)
                ldsm_x4(af[mt],
                        sA + (uint32_t)(((arow + mt * 16) * 32 +
                                         (((uint32_t)(kk + acoff)) ^ aswz)) * 4));
#pragma unroll
            for (int p = 0; p < 2; p++) {
                uint32_t tmp[4];
                ldsm_x4(tmp,
                        sB + (uint32_t)(((brow + p * 16) * 32 +
                                         (((uint32_t)(kk + bcoff)) ^ bswz)) * 4));
                bf[2 * p][0] = tmp[0]; bf[2 * p][1] = tmp[1];
                bf[2 * p + 1][0] = tmp[2]; bf[2 * p + 1][1] = tmp[3];
            }
#pragma unroll
            for (int mt = 0; mt < 4; mt++)
#pragma unroll
                for (int nt = 0; nt < 4; nt++)
                    mma_tf32(acc[mt][nt], af[mt], bf[nt]);
        }
        __syncthreads();
        st = (st + 1) % NSTAGE;
    }

#pragma unroll
    for (int mt = 0; mt < 4; mt++) {
#pragma unroll
        for (int nt = 0; nt < 4; nt++) {
            int m = m0 + mw * 64 + mt * 16 + lr;
            int n = n0 + nw * 32 + nt * 8 + lc * 2;
            float b0 = bias[n], b1 = bias[n + 1];
#pragma unroll
            for (int half = 0; half < 2; half++) {
                int mm = m + half * 8;
                float v0 = acc[mt][nt][half * 2 + 0] + b0;
                float v1 = acc[mt][nt][half * 2 + 1] + b1;
                if (SPLIT) {
                    v0 = __uint_as_float(f2tf(v0 * outScale));
                    v1 = __uint_as_float(f2tf(v1 * outScale));
                    int bb = mm / S_LEN, s = mm % S_LEN;
                    int h = n / DK, d = n % DK;
                    float* dst = &C[((size_t)(bb * NH + h) * S_LEN + s) * DK + d];
                    dst[0] = v0; dst[1] = v1;
                } else {
                    float* dst = &C[(size_t)mm * NU + n];
                    dst[0] = v0; dst[1] = v1;
                }
            }
        }
    }
}

__global__ __launch_bounds__(256, 2) void gemm_qkv_kernel(
    const float* __restrict__ X0, const float* __restrict__ X1,
    const float* __restrict__ X2,
    const float* __restrict__ W0, const float* __restrict__ W1,
    const float* __restrict__ W2,
    const float* __restrict__ b0, const float* __restrict__ b1,
    const float* __restrict__ b2,
    float* __restrict__ C0, float* __restrict__ C1, float* __restrict__ C2) {
    extern __shared__ char smem[];
    const int z = blockIdx.z;
    const float* X = (z == 0) ? X0 : (z == 1) ? X1 : X2;
    const float* W = (z == 0) ? W0 : (z == 1) ? W1 : W2;
    const float* bias = (z == 0) ? b0 : (z == 1) ? b1 : b2;
    float* C = (z == 0) ? C0 : (z == 1) ? C1 : C2;
    float scale = (z == 0) ? QSCALE_F : 1.0f;
    gemm_body<true>(X, W, bias, C, smem, blockIdx.y * 128, blockIdx.x * 128, scale);
}

__global__ __launch_bounds__(256, 2) void gemm_out_kernel(
    const float* __restrict__ X, const float* __restrict__ W,
    const float* __restrict__ bias, float* __restrict__ C) {
    extern __shared__ char smem[];
    gemm_body<false>(X, W, bias, C, smem, blockIdx.y * 128, blockIdx.x * 128, 1.0f);
}

// ───────────── Flash attention, tf32 mma.sync + ldmatrix ─────────────
// K b-frags and P a-frags via ldmatrix (padded strides are conflict-free:
// stride 68 floats -> 16B-group = row mod 8). V stays scalar (k-major layout).
#define LDQ 68
#define LDK 68
#define LDV 72
#define LDP 68
#define FA_KS_F (64 * LDK)
#define FA_VS_F (64 * LDV)
#define FA_QP_F (64 * LDQ)
#define FA_PS_F (16 * LDP)
#define FA_SMEM ((2 * FA_KS_F + 2 * FA_VS_F + FA_QP_F) * 4)

__global__ __launch_bounds__(128, 2) void flash_mma_kernel(
    const float* __restrict__ Q, const float* __restrict__ K,
    const float* __restrict__ V, float* __restrict__ O) {
    extern __shared__ float sm[];
    float* Ks = sm;
    float* Vs = Ks + 2 * FA_KS_F;
    float* QPs = Vs + 2 * FA_VS_F;

    const int qt = (int)gridDim.x - 1 - (int)blockIdx.x;   // longest first
    const int h = blockIdx.y, b = blockIdx.z;
    const int q0 = qt * 64;
    const size_t base = (size_t)((b * NH + h) * S_LEN) * DK;
    const float* qb = Q + base + (size_t)q0 * DK;
    const float* kb = K + base;
    const float* vb = V + base;

    const int t = threadIdx.x;
    const int lane = t & 31, warp = t >> 5;
    const int lr = lane >> 2, lc = lane & 3;

    const uint32_t uK = smem_to_u32(Ks);
    const uint32_t uV = smem_to_u32(Vs);
    const uint32_t uQ = smem_to_u32(QPs);

#pragma unroll
    for (int i = 0; i < 8; i++) {
        int j = i * 128 + t;
        int r = j >> 4, c16 = j & 15;
        cp_async16(uQ + (uint32_t)(r * LDQ + c16 * 4) * 4, qb + r * DK + c16 * 4);
    }

    auto load_kv = [&](int st, int kt) {
        int k0 = kt * 64;
#pragma unroll
        for (int i = 0; i < 16; i++) {
            int j = i * 128 + t;
            int mat = j >> 10;                 // 0 = K, 1 = V
            int idx = j & 1023;
            int r = idx >> 4, c16 = idx & 15;
            if (mat == 0)
                cp_async16(uK + (uint32_t)(st * FA_KS_F + r * LDK + c16 * 4) * 4,
                           kb + (size_t)(k0 + r) * DK + c16 * 4);
            else
                cp_async16(uV + (uint32_t)(st * FA_VS_F + r * LDV + c16 * 4) * 4,
                           vb + (size_t)(k0 + r) * DK + c16 * 4);
        }
        CP_ASYNC_COMMIT();
    };

    load_kv(0, 0);

    // ldmatrix lane geometry
    const int g = lane >> 3, li = lane & 7;
    const int kbrow = ((g >> 1) << 3) + li;   // K n-row (nt-pair p=0)
    const int kbcoff = (g & 1) << 2;
    const int prow = ((g & 1) << 3) + li;     // P row (a-frag)
    const int pcoff = (g >> 1) << 2;

    uint32_t qa[8][4];
    float o[8][4] = {};
    float mA = -1e30f, mB = -1e30f, lA = 0.f, lB = 0.f;
    float* Pw = QPs + warp * FA_PS_F;
    const uint32_t uPw = uQ + (uint32_t)(warp * FA_PS_F) * 4;
    const int rowA = warp * 16 + lr;

    const int last = qt;
    for (int kt = 0; kt <= last; kt++) {
        const int st = kt & 1;
        if (kt < last) { load_kv(st ^ 1, kt + 1); CP_ASYNC_WAIT(1); }
        else           { CP_ASYNC_WAIT(0); }
        __syncthreads();

        if (kt == 0) {
#pragma unroll
            for (int kc = 0; kc < 8; kc++) {
                int c = kc * 8 + lc;
                qa[kc][0] = __float_as_uint(QPs[rowA * LDQ + c]);
                qa[kc][1] = __float_as_uint(QPs[(rowA + 8) * LDQ + c]);
                qa[kc][2] = __float_as_uint(QPs[rowA * LDQ + c + 4]);
                qa[kc][3] = __float_as_uint(QPs[(rowA + 8) * LDQ + c + 4]);
            }
            __syncwarp();
        }

        const uint32_t uKst = uK + (uint32_t)(st * FA_KS_F) * 4;
        const float* Vst = Vs + st * FA_VS_F;

        // S = Q K^T — K b-frags via ldmatrix (4 LDSM per kc for 8 nt)
        float s[8][4] = {};
#pragma unroll
        for (int kc = 0; kc < 8; kc++) {
            uint32_t bf[8][2];
#pragma unroll
            for (int p = 0; p < 4; p++) {
                uint32_t tmp[4];
                ldsm_x4(tmp, uKst + (uint32_t)(((p * 16 + kbrow) * LDK +
                                                kc * 8 + kbcoff) * 4));
                bf[2 * p][0] = tmp[0]; bf[2 * p][1] = tmp[1];
                bf[2 * p + 1][0] = tmp[2]; bf[2 * p + 1][1] = tmp[3];
            }
#pragma unroll
            for (int nt = 0; nt < 8; nt++)
                mma_tf32(s[nt], qa[kc], bf[nt]);
        }

        const int gA = q0 + rowA, gB = gA + 8;
        if (kt == last) {
            const int j0b = kt * 64;
#pragma unroll
            for (int nt = 0; nt < 8; nt++) {
                int j0 = j0b + nt * 8 + 2 * lc;
                if (j0 > gA)     s[nt][0] = -1e10f;
                if (j0 + 1 > gA) s[nt][1] = -1e10f;
                if (j0 > gB)     s[nt][2] = -1e10f;
                if (j0 + 1 > gB) s[nt][3] = -1e10f;
            }
        }

        float tmA = -1e30f, tmB = -1e30f;
#pragma unroll
        for (int nt = 0; nt < 8; nt++) {
            tmA = fmaxf(tmA, fmaxf(s[nt][0], s[nt][1]));
            tmB = fmaxf(tmB, fmaxf(s[nt][2], s[nt][3]));
        }
        tmA = fmaxf(tmA, __shfl_xor_sync(0xffffffff, tmA, 1));
        tmA = fmaxf(tmA, __shfl_xor_sync(0xffffffff, tmA, 2));
        tmB = fmaxf(tmB, __shfl_xor_sync(0xffffffff, tmB, 1));
        tmB = fmaxf(tmB, __shfl_xor_sync(0xffffffff, tmB, 2));
        float mnA = fmaxf(mA, tmA), mnB = fmaxf(mB, tmB);
        float cA = fast_exp2(mA - mnA), cB = fast_exp2(mB - mnB);
        float sumA = 0.f, sumB = 0.f;
#pragma unroll
        for (int nt = 0; nt < 8; nt++) {
            float p0 = fast_exp2(s[nt][0] - mnA);
            float p1 = fast_exp2(s[nt][1] - mnA);
            float p2 = fast_exp2(s[nt][2] - mnB);
            float p3 = fast_exp2(s[nt][3] - mnB);
            sumA += p0 + p1; sumB += p2 + p3;
            float2* d0 = (float2*)&Pw[lr * LDP + nt * 8 + 2 * lc];
            *d0 = make_float2(__uint_as_float(f2tf(p0)), __uint_as_float(f2tf(p1)));
            float2* d1 = (float2*)&Pw[(lr + 8) * LDP + nt * 8 + 2 * lc];
            *d1 = make_float2(__uint_as_float(f2tf(p2)), __uint_as_float(f2tf(p3)));
        }
        sumA += __shfl_xor_sync(0xffffffff, sumA, 1);
        sumA += __shfl_xor_sync(0xffffffff, sumA, 2);
        sumB += __shfl_xor_sync(0xffffffff, sumB, 1);
        sumB += __shfl_xor_sync(0xffffffff, sumB, 2);
        lA = lA * cA + sumA; lB = lB * cB + sumB;
        mA = mnA; mB = mnB;
#pragma unroll
        for (int nt = 0; nt < 8; nt++) {
            o[nt][0] *= cA; o[nt][1] *= cA;
            o[nt][2] *= cB; o[nt][3] *= cB;
        }
        __syncwarp();

        // O += P V — P a-frags via ldmatrix, V scalar
#pragma unroll
        for (int kc = 0; kc < 8; kc++) {
            uint32_t pa[4];
            ldsm_x4(pa, uPw + (uint32_t)((prow * LDP + kc * 8 + pcoff) * 4));
#pragma unroll
            for (int nt = 0; nt < 8; nt++) {
                uint32_t bf2[2];
                bf2[0] = __float_as_uint(Vst[(kc * 8 + lc) * LDV + nt * 8 + lr]);
                bf2[1] = __float_as_uint(Vst[(kc * 8 + lc + 4) * LDV + nt * 8 + lr]);
                mma_tf32(o[nt], pa, bf2);
            }
        }
        __syncthreads();
    }

    const float invA = 1.f / lA, invB = 1.f / lB;
    const int qgA = q0 + rowA;
#pragma unroll
    for (int nt = 0; nt < 8; nt++) {
        int n = h * DK + nt * 8 + 2 * lc;
        float2* dA = (float2*)&O[(size_t)(b * S_LEN + qgA) * NU + n];
        *dA = make_float2(__uint_as_float(f2tf(o[nt][0] * invA)),
                          __uint_as_float(f2tf(o[nt][1] * invA)));
        float2* dB = (float2*)&O[(size_t)(b * S_LEN + qgA + 8) * NU + n];
        *dB = make_float2(__uint_as_float(f2tf(o[nt][2] * invB)),
                          __uint_as_float(f2tf(o[nt][3] * invB)));
    }
}

extern "C" void kernel_launch(void* const* d_in, const int* in_sizes, int n_in,
                              void* d_out, int out_size) {
    const float* query = (const float*)d_in[0];
    const float* key_  = (const float*)d_in[1];
    const float* value = (const float*)d_in[2];
    // d_in[3] = mask (int32) — causal tril, handled analytically.
    const float* Wq = (const float*)d_in[4];
    const float* bq = (const float*)d_in[5];
    const float* Wk = (const float*)d_in[6];
    const float* bk = (const float*)d_in[7];
    const float* Wv = (const float*)d_in[8];
    const float* bv = (const float*)d_in[9];
    const float* Wo = (const float*)d_in[10];
    const float* bo = (const float*)d_in[11];

    float *pq, *pk, *pv, *pa;
    float *pxq, *pxk, *pxv, *pwq, *pwk, *pwv, *pwo;
    cudaGetSymbolAddress((void**)&pq, g_q);
    cudaGetSymbolAddress((void**)&pk, g_k);
    cudaGetSymbolAddress((void**)&pv, g_v);
    cudaGetSymbolAddress((void**)&pa, g_attn);
    cudaGetSymbolAddress((void**)&pxq, g_xq);
    cudaGetSymbolAddress((void**)&pxk, g_xk);
    cudaGetSymbolAddress((void**)&pxv, g_xv);
    cudaGetSymbolAddress((void**)&pwq, g_wq);
    cudaGetSymbolAddress((void**)&pwk, g_wk);
    cudaGetSymbolAddress((void**)&pwv, g_wv);
    cudaGetSymbolAddress((void**)&pwo, g_wo);

    cudaFuncSetAttribute(gemm_qkv_kernel,
                         cudaFuncAttributeMaxDynamicSharedMemorySize, GEMM_SMEM);
    cudaFuncSetAttribute(gemm_out_kernel,
                         cudaFuncAttributeMaxDynamicSharedMemorySize, GEMM_SMEM);
    cudaFuncSetAttribute(flash_mma_kernel,
                         cudaFuncAttributeMaxDynamicSharedMemorySize, FA_SMEM);

    preround_kernel<<<dim3(1024, 1, 7), 256>>>(
        query, key_, value, Wq, Wk, Wv, Wo,
        pxq, pxk, pxv, pwq, pwk, pwv, pwo);

    gemm_qkv_kernel<<<dim3(NU / 128, MROWS / 128, 3), 256, GEMM_SMEM>>>(
        pxq, pxk, pxv, pwq, pwk, pwv, bq, bk, bv, pq, pk, pv);

    flash_mma_kernel<<<dim3(S_LEN / 64, NH, BATCH), 128, FA_SMEM>>>(pq, pk, pv, pa);

    gemm_out_kernel<<<dim3(NU / 128, MROWS / 128), 256, GEMM_SMEM>>>(
        pa, pwo, bo, (float*)d_out);
}

// round 16
// speedup vs baseline: 1.8805x; 1.8805x over previous
#include <cuda_runtime.h>
#include <cuda_fp16.h>
#include <cstdint>

#define BATCH 2
#define S_LEN 2048
#define NU 1024
#define NH 16
#define DK 64
#define MROWS (BATCH * S_LEN)

// Scratch. GEMM operands live as fp16; Q/K/V for flash live as fp32 tf32-bits
// (Q pre-scaled by 1/sqrt(Dk)*log2e) so flash loads fragments with zero cvt.
__device__ float g_q[BATCH * NH * S_LEN * DK];
__device__ float g_k[BATCH * NH * S_LEN * DK];
__device__ float g_v[BATCH * NH * S_LEN * DK];
__device__ __half g_attn[MROWS * NU];
// fp16 copies of harness inputs.
__device__ __half g_xq[MROWS * NU];
__device__ __half g_xk[MROWS * NU];
__device__ __half g_xv[MROWS * NU];
__device__ __half g_wq[NU * NU];
__device__ __half g_wk[NU * NU];
__device__ __half g_wv[NU * NU];
__device__ __half g_wo[NU * NU];

#define QSCALE_F (0.125f * 1.44269504088896f)   // 1/sqrt(Dk) * log2(e)

// ───────────────────────── helpers ─────────────────────────
__device__ __forceinline__ uint32_t smem_to_u32(const void* p) {
    uint32_t a;
    asm("{ .reg .u64 t; cvta.to.shared.u64 t, %1; cvt.u32.u64 %0, t; }"
        : "=r"(a) : "l"(p));
    return a;
}
__device__ __forceinline__ void cp_async16(uint32_t dst, const void* src) {
    asm volatile("cp.async.cg.shared.global [%0], [%1], 16;" :: "r"(dst), "l"(src) : "memory");
}
#define CP_ASYNC_COMMIT() asm volatile("cp.async.commit_group;" ::: "memory")
#define CP_ASYNC_WAIT(n)  asm volatile("cp.async.wait_group %0;" :: "n"(n) : "memory")

__device__ __forceinline__ uint32_t f2tf(float f) {
    uint32_t u;
    asm("cvt.rna.tf32.f32 %0, %1;" : "=r"(u) : "f"(f));
    return u;
}
__device__ __forceinline__ float fast_exp2(float x) {
    float y;
    asm("ex2.approx.f32 %0, %1;" : "=f"(y) : "f"(x));
    return y;
}
__device__ __forceinline__ void mma_tf32(float* c, const uint32_t* a, const uint32_t* b) {
    asm volatile(
        "mma.sync.aligned.m16n8k8.row.col.f32.tf32.tf32.f32 "
        "{%0,%1,%2,%3}, {%4,%5,%6,%7}, {%8,%9}, {%0,%1,%2,%3};"
        : "+f"(c[0]), "+f"(c[1]), "+f"(c[2]), "+f"(c[3])
        : "r"(a[0]), "r"(a[1]), "r"(a[2]), "r"(a[3]), "r"(b[0]), "r"(b[1]));
}
__device__ __forceinline__ void mma_f16(float* c, const uint32_t* a, const uint32_t* b) {
    asm volatile(
        "mma.sync.aligned.m16n8k16.row.col.f32.f16.f16.f32 "
        "{%0,%1,%2,%3}, {%4,%5,%6,%7}, {%8,%9}, {%0,%1,%2,%3};"
        : "+f"(c[0]), "+f"(c[1]), "+f"(c[2]), "+f"(c[3])
        : "r"(a[0]), "r"(a[1]), "r"(a[2]), "r"(a[3]), "r"(b[0]), "r"(b[1]));
}

// ─────────── input convert: fp32 -> fp16 ───────────
__global__ __launch_bounds__(256) void preround_kernel(
    const float* __restrict__ x0, const float* __restrict__ x1,
    const float* __restrict__ x2,
    const float* __restrict__ w0, const float* __restrict__ w1,
    const float* __restrict__ w2, const float* __restrict__ w3,
    __half* __restrict__ ox0, __half* __restrict__ ox1, __half* __restrict__ ox2,
    __half* __restrict__ ow0, __half* __restrict__ ow1, __half* __restrict__ ow2,
    __half* __restrict__ ow3) {
    const int z = blockIdx.z;
    const float* in;
    __half* out;
    int n4;
    switch (z) {
        case 0: in = x0; out = ox0; n4 = MROWS * NU / 4; break;
        case 1: in = x1; out = ox1; n4 = MROWS * NU / 4; break;
        case 2: in = x2; out = ox2; n4 = MROWS * NU / 4; break;
        case 3: in = w0; out = ow0; n4 = NU * NU / 4; break;
        case 4: in = w1; out = ow1; n4 = NU * NU / 4; break;
        case 5: in = w2; out = ow2; n4 = NU * NU / 4; break;
        default: in = w3; out = ow3; n4 = NU * NU / 4; break;
    }
    for (int i = blockIdx.x * 256 + threadIdx.x; i < n4; i += gridDim.x * 256) {
        float4 v = ((const float4*)in)[i];
        __half2* o2 = (__half2*)out + 2 * i;
        o2[0] = __floats2half2_rn(v.x, v.y);
        o2[1] = __floats2half2_rn(v.z, v.w);
    }
}

// ───────────────── fp16 mma.sync GEMM ─────────────────
// C[M=4096,N=1024] = X @ W^T + bias, fp16 inputs, fp32 accumulate.
// CTA 128x128, 8 warps each 64x32, K-chunk 64 halves (128B rows, same swizzle
// geometry as the tf32 version), 3-stage cp.async pipeline.
#define BKH 64
#define TILE_BYTES 16384                    // 128 rows * 128 B
#define STAGE_BYTES (2 * TILE_BYTES)
#define NSTAGE 3
#define GEMM_SMEM (NSTAGE * STAGE_BYTES)

// swizzled byte offset of half index hh in row r (row = 128 B, 16B chunks XOR r&7)
#define SWH(r, hh) ((r) * 128 + (((((hh) >> 3) ^ ((r) & 7)) << 4) | (((hh) & 7) * 2)))

template <bool SPLIT>
__device__ __forceinline__ void gemm_body(
    const __half* __restrict__ X, const __half* __restrict__ W,
    const float* __restrict__ bias, float* __restrict__ C,
    char* smem, int m0, int n0, float outScale) {
    const uint32_t sb = smem_to_u32(smem);
    const int t = threadIdx.x;
    const int lane = t & 31, warp = t >> 5;
    const int mw = warp & 1, nw = warp >> 1;
    const int lr = lane >> 2, lc = lane & 3;

    const __half* gA = X + (size_t)m0 * NU;
    const __half* gB = W + (size_t)n0 * NU;

    auto load_tiles = [&](int st, int kt) {
#pragma unroll
        for (int i = 0; i < 8; i++) {
            int j = i * 256 + t;
            int mat = j >> 10;
            int idx = j & 1023;
            int r = idx >> 3, c16 = idx & 7;
            const __half* g = (mat ? gB : gA) + (size_t)r * NU + kt * BKH + c16 * 8;
            uint32_t off = (uint32_t)(r * 128 + ((c16 * 16) ^ ((r & 7) << 4)));
            cp_async16(sb + st * STAGE_BYTES + mat * TILE_BYTES + off, g);
        }
        CP_ASYNC_COMMIT();
    };

    float acc[4][4][4] = {};

    const int NKT = NU / BKH;                // 16
    load_tiles(0, 0);
    load_tiles(1, 1);
    int st = 0;
    for (int kt = 0; kt < NKT; kt++) {
        if (kt + 2 < NKT) { load_tiles((st + 2) % NSTAGE, kt + 2); CP_ASYNC_WAIT(2); }
        else if (kt + 1 < NKT) { CP_ASYNC_WAIT(1); }
        else { CP_ASYNC_WAIT(0); }
        __syncthreads();

        const char* As = smem + st * STAGE_BYTES;
        const char* Bs = As + TILE_BYTES;
#pragma unroll
        for (int kk = 0; kk < 4; kk++) {      // 4 x K=16
            const int h0 = kk * 16 + 2 * lc;
            const int h1 = h0 + 8;
            uint32_t af[4][4], bf[4][2];
#pragma unroll
            for (int mt = 0; mt < 4; mt++) {
                int r = mw * 64 + mt * 16 + lr;
                int r8 = r + 8;
                af[mt][0] = *(const uint32_t*)(As + SWH(r, h0));
                af[mt][1] = *(const uint32_t*)(As + SWH(r8, h0));
                af[mt][2] = *(const uint32_t*)(As + SWH(r, h1));
                af[mt][3] = *(const uint32_t*)(As + SWH(r8, h1));
            }
#pragma unroll
            for (int nt = 0; nt < 4; nt++) {
                int n = nw * 32 + nt * 8 + lr;
                bf[nt][0] = *(const uint32_t*)(Bs + SWH(n, h0));
                bf[nt][1] = *(const uint32_t*)(Bs + SWH(n, h1));
            }
#pragma unroll
            for (int mt = 0; mt < 4; mt++)
#pragma unroll
                for (int nt = 0; nt < 4; nt++)
                    mma_f16(acc[mt][nt], af[mt], bf[nt]);
        }
        __syncthreads();
        st = (st + 1) % NSTAGE;
    }

#pragma unroll
    for (int mt = 0; mt < 4; mt++) {
#pragma unroll
        for (int nt = 0; nt < 4; nt++) {
            int m = m0 + mw * 64 + mt * 16 + lr;
            int n = n0 + nw * 32 + nt * 8 + lc * 2;
            float b0 = bias[n], b1 = bias[n + 1];
#pragma unroll
            for (int half = 0; half < 2; half++) {
                int mm = m + half * 8;
                float v0 = acc[mt][nt][half * 2 + 0] + b0;
                float v1 = acc[mt][nt][half * 2 + 1] + b1;
                if (SPLIT) {
                    // tf32 pre-round + scale: flash consumes these bits directly
                    v0 = __uint_as_float(f2tf(v0 * outScale));
                    v1 = __uint_as_float(f2tf(v1 * outScale));
                    int bb = mm / S_LEN, s = mm % S_LEN;
                    int h = n / DK, d = n % DK;
                    float* dst = &C[((size_t)(bb * NH + h) * S_LEN + s) * DK + d];
                    dst[0] = v0; dst[1] = v1;
                } else {
                    float* dst = &C[(size_t)mm * NU + n];
                    dst[0] = v0; dst[1] = v1;
                }
            }
        }
    }
}

__global__ __launch_bounds__(256, 2) void gemm_qkv_kernel(
    const __half* __restrict__ X0, const __half* __restrict__ X1,
    const __half* __restrict__ X2,
    const __half* __restrict__ W0, const __half* __restrict__ W1,
    const __half* __restrict__ W2,
    const float* __restrict__ b0, const float* __restrict__ b1,
    const float* __restrict__ b2,
    float* __restrict__ C0, float* __restrict__ C1, float* __restrict__ C2) {
    extern __shared__ char smem[];
    const int z = blockIdx.z;
    const __half* X = (z == 0) ? X0 : (z == 1) ? X1 : X2;
    const __half* W = (z == 0) ? W0 : (z == 1) ? W1 : W2;
    const float* bias = (z == 0) ? b0 : (z == 1) ? b1 : b2;
    float* C = (z == 0) ? C0 : (z == 1) ? C1 : C2;
    float scale = (z == 0) ? QSCALE_F : 1.0f;
    gemm_body<true>(X, W, bias, C, smem, blockIdx.y * 128, blockIdx.x * 128, scale);
}

__global__ __launch_bounds__(256, 2) void gemm_out_kernel(
    const __half* __restrict__ X, const __half* __restrict__ W,
    const float* __restrict__ bias, float* __restrict__ C) {
    extern __shared__ char smem[];
    gemm_body<false>(X, W, bias, C, smem, blockIdx.y * 128, blockIdx.x * 128, 1.0f);
}

// ───────────── Flash attention, tf32 mma.sync (R12 version, scalar LDS) ─────────────
// CTA: 64 q-rows x (head, batch), 4 warps x 16-row strips, 128 threads.
// Q/K/V scratch already tf32 bits (Q pre-scaled) -> zero cvt. Epilogue writes
// g_attn as fp16 (A operand of the fp16 gemm_out).
#define LDQ 68
#define LDK 68
#define LDV 72
#define LDP 68
#define FA_KS_F (64 * LDK)
#define FA_VS_F (64 * LDV)
#define FA_QP_F (64 * LDQ)
#define FA_PS_F (16 * LDP)
#define FA_SMEM ((2 * FA_KS_F + 2 * FA_VS_F + FA_QP_F) * 4)

__global__ __launch_bounds__(128, 2) void flash_mma_kernel(
    const float* __restrict__ Q, const float* __restrict__ K,
    const float* __restrict__ V, __half* __restrict__ O) {
    extern __shared__ float sm[];
    float* Ks = sm;
    float* Vs = Ks + 2 * FA_KS_F;
    float* QPs = Vs + 2 * FA_VS_F;

    const int qt = (int)gridDim.x - 1 - (int)blockIdx.x;   // longest first
    const int h = blockIdx.y, b = blockIdx.z;
    const int q0 = qt * 64;
    const size_t base = (size_t)((b * NH + h) * S_LEN) * DK;
    const float* qb = Q + base + (size_t)q0 * DK;
    const float* kb = K + base;
    const float* vb = V + base;

    const int t = threadIdx.x;
    const int lane = t & 31, warp = t >> 5;
    const int lr = lane >> 2, lc = lane & 3;

    const uint32_t uK = smem_to_u32(Ks);
    const uint32_t uV = smem_to_u32(Vs);
    const uint32_t uQ = smem_to_u32(QPs);

#pragma unroll
    for (int i = 0; i < 8; i++) {
        int j = i * 128 + t;
        int r = j >> 4, c16 = j & 15;
        cp_async16(uQ + (uint32_t)(r * LDQ + c16 * 4) * 4, qb + r * DK + c16 * 4);
    }

    auto load_kv = [&](int st, int kt) {
        int k0 = kt * 64;
#pragma unroll
        for (int i = 0; i < 16; i++) {
            int j = i * 128 + t;
            int mat = j >> 10;                 // 0 = K, 1 = V
            int idx = j & 1023;
            int r = idx >> 4, c16 = idx & 15;
            if (mat == 0)
                cp_async16(uK + (uint32_t)(st * FA_KS_F + r * LDK + c16 * 4) * 4,
                           kb + (size_t)(k0 + r) * DK + c16 * 4);
            else
                cp_async16(uV + (uint32_t)(st * FA_VS_F + r * LDV + c16 * 4) * 4,
                           vb + (size_t)(k0 + r) * DK + c16 * 4);
        }
        CP_ASYNC_COMMIT();
    };

    load_kv(0, 0);

    uint32_t qa[8][4];
    float o[8][4] = {};
    float mA = -1e30f, mB = -1e30f, lA = 0.f, lB = 0.f;
    float* Pw = QPs + warp * FA_PS_F;
    const int rowA = warp * 16 + lr;

    const int last = qt;
    for (int kt = 0; kt <= last; kt++) {
        const int st = kt & 1;
        if (kt < last) { load_kv(st ^ 1, kt + 1); CP_ASYNC_WAIT(1); }
        else           { CP_ASYNC_WAIT(0); }
        __syncthreads();

        if (kt == 0) {
#pragma unroll
            for (int kc = 0; kc < 8; kc++) {
                int c = kc * 8 + lc;
                qa[kc][0] = __float_as_uint(QPs[rowA * LDQ + c]);
                qa[kc][1] = __float_as_uint(QPs[(rowA + 8) * LDQ + c]);
                qa[kc][2] = __float_as_uint(QPs[rowA * LDQ + c + 4]);
                qa[kc][3] = __float_as_uint(QPs[(rowA + 8) * LDQ + c + 4]);
            }
            __syncwarp();
        }

        const float* Kst = Ks + st * FA_KS_F;
        const float* Vst = Vs + st * FA_VS_F;

        float s[8][4] = {};
#pragma unroll
        for (int kc = 0; kc < 8; kc++) {
#pragma unroll
            for (int nt = 0; nt < 8; nt++) {
                uint32_t bf[2];
                const float* kp = &Kst[(nt * 8 + lr) * LDK + kc * 8 + lc];
                bf[0] = __float_as_uint(kp[0]);
                bf[1] = __float_as_uint(kp[4]);
                mma_tf32(s[nt], qa[kc], bf);
            }
        }

        const int gA = q0 + rowA, gB = gA + 8;
        if (kt == last) {
            const int j0b = kt * 64;
#pragma unroll
            for (int nt = 0; nt < 8; nt++) {
                int j0 = j0b + nt * 8 + 2 * lc;
                if (j0 > gA)     s[nt][0] = -1e10f;
                if (j0 + 1 > gA) s[nt][1] = -1e10f;
                if (j0 > gB)     s[nt][2] = -1e10f;
                if (j0 + 1 > gB) s[nt][3] = -1e10f;
            }
        }

        float tmA = -1e30f, tmB = -1e30f;
#pragma unroll
        for (int nt = 0; nt < 8; nt++) {
            tmA = fmaxf(tmA, fmaxf(s[nt][0], s[nt][1]));
            tmB = fmaxf(tmB, fmaxf(s[nt][2], s[nt][3]));
        }
        tmA = fmaxf(tmA, __shfl_xor_sync(0xffffffff, tmA, 1));
        tmA = fmaxf(tmA, __shfl_xor_sync(0xffffffff, tmA, 2));
        tmB = fmaxf(tmB, __shfl_xor_sync(0xffffffff, tmB, 1));
        tmB = fmaxf(tmB, __shfl_xor_sync(0xffffffff, tmB, 2));
        float mnA = fmaxf(mA, tmA), mnB = fmaxf(mB, tmB);
        float cA = fast_exp2(mA - mnA), cB = fast_exp2(mB - mnB);
        float sumA = 0.f, sumB = 0.f;
#pragma unroll
        for (int nt = 0; nt < 8; nt++) {
            float p0 = fast_exp2(s[nt][0] - mnA);
            float p1 = fast_exp2(s[nt][1] - mnA);
            float p2 = fast_exp2(s[nt][2] - mnB);
            float p3 = fast_exp2(s[nt][3] - mnB);
            sumA += p0 + p1; sumB += p2 + p3;
            float2* d0 = (float2*)&Pw[lr * LDP + nt * 8 + 2 * lc];
            *d0 = make_float2(__uint_as_float(f2tf(p0)), __uint_as_float(f2tf(p1)));
            float2* d1 = (float2*)&Pw[(lr + 8) * LDP + nt * 8 + 2 * lc];
            *d1 = make_float2(__uint_as_float(f2tf(p2)), __uint_as_float(f2tf(p3)));
        }
        sumA += __shfl_xor_sync(0xffffffff, sumA, 1);
        sumA += __shfl_xor_sync(0xffffffff, sumA, 2);
        sumB += __shfl_xor_sync(0xffffffff, sumB, 1);
        sumB += __shfl_xor_sync(0xffffffff, sumB, 2);
        lA = lA * cA + sumA; lB = lB * cB + sumB;
        mA = mnA; mB = mnB;
#pragma unroll
        for (int nt = 0; nt < 8; nt++) {
            o[nt][0] *= cA; o[nt][1] *= cA;
            o[nt][2] *= cB; o[nt][3] *= cB;
        }
        __syncwarp();

#pragma unroll
        for (int kc = 0; kc < 8; kc++) {
            uint32_t pa[4];
            pa[0] = __float_as_uint(Pw[lr * LDP + kc * 8 + lc]);
            pa[1] = __float_as_uint(Pw[(lr + 8) * LDP + kc * 8 + lc]);
            pa[2] = __float_as_uint(Pw[lr * LDP + kc * 8 + lc + 4]);
            pa[3] = __float_as_uint(Pw[(lr + 8) * LDP + kc * 8 + lc + 4]);
#pragma unroll
            for (int nt = 0; nt < 8; nt++) {
                uint32_t bf[2];
                bf[0] = __float_as_uint(Vst[(kc * 8 + lc) * LDV + nt * 8 + lr]);
                bf[1] = __float_as_uint(Vst[(kc * 8 + lc + 4) * LDV + nt * 8 + lr]);
                mma_tf32(o[nt], pa, bf);
            }
        }
        __syncthreads();
    }

    // Epilogue: normalize, write fp16 merged-head layout [B,S,U]
    const float invA = 1.f / lA, invB = 1.f / lB;
    const int qgA = q0 + rowA;
#pragma unroll
    for (int nt = 0; nt < 8; nt++) {
        int n = h * DK + nt * 8 + 2 * lc;
        __half2* dA = (__half2*)&O[(size_t)(b * S_LEN + qgA) * NU + n];
        *dA = __floats2half2_rn(o[nt][0] * invA, o[nt][1] * invA);
        __half2* dB = (__half2*)&O[(size_t)(b * S_LEN + qgA + 8) * NU + n];
        *dB = __floats2half2_rn(o[nt][2] * invB, o[nt][3] * invB);
    }
}

extern "C" void kernel_launch(void* const* d_in, const int* in_sizes, int n_in,
                              void* d_out, int out_size) {
    const float* query = (const float*)d_in[0];
    const float* key_  = (const float*)d_in[1];
    const float* value = (const float*)d_in[2];
    // d_in[3] = mask (int32) — causal tril, handled analytically.
    const float* Wq = (const float*)d_in[4];
    const float* bq = (const float*)d_in[5];
    const float* Wk = (const float*)d_in[6];
    const float* bk = (const float*)d_in[7];
    const float* Wv = (const float*)d_in[8];
    const float* bv = (const float*)d_in[9];
    const float* Wo = (const float*)d_in[10];
    const float* bo = (const float*)d_in[11];

    float *pq, *pk, *pv;
    __half *pa, *pxq, *pxk, *pxv, *pwq, *pwk, *pwv, *pwo;
    cudaGetSymbolAddress((void**)&pq, g_q);
    cudaGetSymbolAddress((void**)&pk, g_k);
    cudaGetSymbolAddress((void**)&pv, g_v);
    cudaGetSymbolAddress((void**)&pa, g_attn);
    cudaGetSymbolAddress((void**)&pxq, g_xq);
    cudaGetSymbolAddress((void**)&pxk, g_xk);
    cudaGetSymbolAddress((void**)&pxv, g_xv);
    cudaGetSymbolAddress((void**)&pwq, g_wq);
    cudaGetSymbolAddress((void**)&pwk, g_wk);
    cudaGetSymbolAddress((void**)&pwv, g_wv);
    cudaGetSymbolAddress((void**)&pwo, g_wo);

    cudaFuncSetAttribute(gemm_qkv_kernel,
                         cudaFuncAttributeMaxDynamicSharedMemorySize, GEMM_SMEM);
    cudaFuncSetAttribute(gemm_out_kernel,
                         cudaFuncAttributeMaxDynamicSharedMemorySize, GEMM_SMEM);
    cudaFuncSetAttribute(flash_mma_kernel,
                         cudaFuncAttributeMaxDynamicSharedMemorySize, FA_SMEM);

    preround_kernel<<<dim3(1024, 1, 7), 256>>>(
        query, key_, value, Wq, Wk, Wv, Wo,
        pxq, pxk, pxv, pwq, pwk, pwv, pwo);

    gemm_qkv_kernel<<<dim3(NU / 128, MROWS / 128, 3), 256, GEMM_SMEM>>>(
        pxq, pxk, pxv, pwq, pwk, pwv, bq, bk, bv, pq, pk, pv);

    flash_mma_kernel<<<dim3(S_LEN / 64, NH, BATCH), 128, FA_SMEM>>>(pq, pk, pv, pa);

    gemm_out_kernel<<<dim3(NU / 128, MROWS / 128), 256, GEMM_SMEM>>>(
        pa, pwo, bo, (float*)d_out);
}

// round 17
// speedup vs baseline: 2.5944x; 1.3796x over previous
#include <cuda_runtime.h>
#include <cuda_fp16.h>
#include <cstdint>

#define BATCH 2
#define S_LEN 2048
#define NU 1024
#define NH 16
#define DK 64
#define MROWS (BATCH * S_LEN)

// Scratch. All GEMM/flash operands fp16 (Q pre-scaled by 1/sqrt(Dk)*log2e).
// g_v is stored TRANSPOSED: [B,H,Dk,S] so PV b-fragments are contiguous half2.
__device__ __half g_q[BATCH * NH * S_LEN * DK];
__device__ __half g_k[BATCH * NH * S_LEN * DK];
__device__ __half g_v[BATCH * NH * DK * S_LEN];
__device__ __half g_attn[MROWS * NU];
// fp16 copies of harness inputs.
__device__ __half g_xq[MROWS * NU];
__device__ __half g_xk[MROWS * NU];
__device__ __half g_xv[MROWS * NU];
__device__ __half g_wq[NU * NU];
__device__ __half g_wk[NU * NU];
__device__ __half g_wv[NU * NU];
__device__ __half g_wo[NU * NU];

#define QSCALE_F (0.125f * 1.44269504088896f)   // 1/sqrt(Dk) * log2(e)

// ───────────────────────── helpers ─────────────────────────
__device__ __forceinline__ uint32_t smem_to_u32(const void* p) {
    uint32_t a;
    asm("{ .reg .u64 t; cvta.to.shared.u64 t, %1; cvt.u32.u64 %0, t; }"
        : "=r"(a) : "l"(p));
    return a;
}
__device__ __forceinline__ void cp_async16(uint32_t dst, const void* src) {
    asm volatile("cp.async.cg.shared.global [%0], [%1], 16;" :: "r"(dst), "l"(src) : "memory");
}
#define CP_ASYNC_COMMIT() asm volatile("cp.async.commit_group;" ::: "memory")
#define CP_ASYNC_WAIT(n)  asm volatile("cp.async.wait_group %0;" :: "n"(n) : "memory")

__device__ __forceinline__ float fast_exp2(float x) {
    float y;
    asm("ex2.approx.f32 %0, %1;" : "=f"(y) : "f"(x));
    return y;
}
__device__ __forceinline__ void mma_f16(float* c, const uint32_t* a, const uint32_t* b) {
    asm volatile(
        "mma.sync.aligned.m16n8k16.row.col.f32.f16.f16.f32 "
        "{%0,%1,%2,%3}, {%4,%5,%6,%7}, {%8,%9}, {%0,%1,%2,%3};"
        : "+f"(c[0]), "+f"(c[1]), "+f"(c[2]), "+f"(c[3])
        : "r"(a[0]), "r"(a[1]), "r"(a[2]), "r"(a[3]), "r"(b[0]), "r"(b[1]));
}

// ─────────── input convert: fp32 -> fp16 ───────────
__global__ __launch_bounds__(256) void preround_kernel(
    const float* __restrict__ x0, const float* __restrict__ x1,
    const float* __restrict__ x2,
    const float* __restrict__ w0, const float* __restrict__ w1,
    const float* __restrict__ w2, const float* __restrict__ w3,
    __half* __restrict__ ox0, __half* __restrict__ ox1, __half* __restrict__ ox2,
    __half* __restrict__ ow0, __half* __restrict__ ow1, __half* __restrict__ ow2,
    __half* __restrict__ ow3) {
    const int z = blockIdx.z;
    const float* in;
    __half* out;
    int n4;
    switch (z) {
        case 0: in = x0; out = ox0; n4 = MROWS * NU / 4; break;
        case 1: in = x1; out = ox1; n4 = MROWS * NU / 4; break;
        case 2: in = x2; out = ox2; n4 = MROWS * NU / 4; break;
        case 3: in = w0; out = ow0; n4 = NU * NU / 4; break;
        case 4: in = w1; out = ow1; n4 = NU * NU / 4; break;
        case 5: in = w2; out = ow2; n4 = NU * NU / 4; break;
        default: in = w3; out = ow3; n4 = NU * NU / 4; break;
    }
    for (int i = blockIdx.x * 256 + threadIdx.x; i < n4; i += gridDim.x * 256) {
        float4 v = ((const float4*)in)[i];
        __half2* o2 = (__half2*)out + 2 * i;
        o2[0] = __floats2half2_rn(v.x, v.y);
        o2[1] = __floats2half2_rn(v.z, v.w);
    }
}

// ───────────────── fp16 mma.sync GEMM ─────────────────
// MODE 0: flat fp32 out. MODE 1: split [B,H,S,Dk] fp16 out (scaled).
// MODE 2: split-transposed [B,H,Dk,S] fp16 out (for V).
#define BKH 64
#define TILE_BYTES 16384                    // 128 rows * 128 B
#define STAGE_BYTES (2 * TILE_BYTES)
#define NSTAGE 3
#define GEMM_SMEM (NSTAGE * STAGE_BYTES)

// swizzled byte offset of half index hh in row r (row = 128 B, 16B chunks XOR r&7)
#define SWH(r, hh) ((r) * 128 + (((((hh) >> 3) ^ ((r) & 7)) << 4) | (((hh) & 7) * 2)))

template <int MODE>
__device__ __forceinline__ void gemm_body(
    const __half* __restrict__ X, const __half* __restrict__ W,
    const float* __restrict__ bias, void* __restrict__ Cv,
    char* smem, int m0, int n0, float outScale) {
    const uint32_t sb = smem_to_u32(smem);
    const int t = threadIdx.x;
    const int lane = t & 31, warp = t >> 5;
    const int mw = warp & 1, nw = warp >> 1;
    const int lr = lane >> 2, lc = lane & 3;

    const __half* gA = X + (size_t)m0 * NU;
    const __half* gB = W + (size_t)n0 * NU;

    auto load_tiles = [&](int st, int kt) {
#pragma unroll
        for (int i = 0; i < 8; i++) {
            int j = i * 256 + t;
            int mat = j >> 10;
            int idx = j & 1023;
            int r = idx >> 3, c16 = idx & 7;
            const __half* g = (mat ? gB : gA) + (size_t)r * NU + kt * BKH + c16 * 8;
            uint32_t off = (uint32_t)(r * 128 + ((c16 * 16) ^ ((r & 7) << 4)));
            cp_async16(sb + st * STAGE_BYTES + mat * TILE_BYTES + off, g);
        }
        CP_ASYNC_COMMIT();
    };

    float acc[4][4][4] = {};

    const int NKT = NU / BKH;                // 16
    load_tiles(0, 0);
    load_tiles(1, 1);
    int st = 0;
    for (int kt = 0; kt < NKT; kt++) {
        if (kt + 2 < NKT) { load_tiles((st + 2) % NSTAGE, kt + 2); CP_ASYNC_WAIT(2); }
        else if (kt + 1 < NKT) { CP_ASYNC_WAIT(1); }
        else { CP_ASYNC_WAIT(0); }
        __syncthreads();

        const char* As = smem + st * STAGE_BYTES;
        const char* Bs = As + TILE_BYTES;
#pragma unroll
        for (int kk = 0; kk < 4; kk++) {      // 4 x K=16
            const int h0 = kk * 16 + 2 * lc;
            const int h1 = h0 + 8;
            uint32_t af[4][4], bf[4][2];
#pragma unroll
            for (int mt = 0; mt < 4; mt++) {
                int r = mw * 64 + mt * 16 + lr;
                int r8 = r + 8;
                af[mt][0] = *(const uint32_t*)(As + SWH(r, h0));
                af[mt][1] = *(const uint32_t*)(As + SWH(r8, h0));
                af[mt][2] = *(const uint32_t*)(As + SWH(r, h1));
                af[mt][3] = *(const uint32_t*)(As + SWH(r8, h1));
            }
#pragma unroll
            for (int nt = 0; nt < 4; nt++) {
                int n = nw * 32 + nt * 8 + lr;
                bf[nt][0] = *(const uint32_t*)(Bs + SWH(n, h0));
                bf[nt][1] = *(const uint32_t*)(Bs + SWH(n, h1));
            }
#pragma unroll
            for (int mt = 0; mt < 4; mt++)
#pragma unroll
                for (int nt = 0; nt < 4; nt++)
                    mma_f16(acc[mt][nt], af[mt], bf[nt]);
        }
        __syncthreads();
        st = (st + 1) % NSTAGE;
    }

#pragma unroll
    for (int mt = 0; mt < 4; mt++) {
#pragma unroll
        for (int nt = 0; nt < 4; nt++) {
            int m = m0 + mw * 64 + mt * 16 + lr;
            int n = n0 + nw * 32 + nt * 8 + lc * 2;
            float b0 = bias[n], b1 = bias[n + 1];
#pragma unroll
            for (int half = 0; half < 2; half++) {
                int mm = m + half * 8;
                float v0 = acc[mt][nt][half * 2 + 0] + b0;
                float v1 = acc[mt][nt][half * 2 + 1] + b1;
                if (MODE == 0) {
                    float* dst = &((float*)Cv)[(size_t)mm * NU + n];
                    dst[0] = v0; dst[1] = v1;
                } else {
                    int bb = mm / S_LEN, s = mm % S_LEN;
                    int hh = n / DK, d = n % DK;
                    __half h0v = __float2half_rn(v0 * outScale);
                    __half h1v = __float2half_rn(v1 * outScale);
                    if (MODE == 1) {
                        __half2* dst = (__half2*)&((__half*)Cv)[
                            ((size_t)(bb * NH + hh) * S_LEN + s) * DK + d];
                        *dst = __halves2half2(h0v, h1v);
                    } else {   // MODE 2: V transposed [B,H,Dk,S]
                        __half* base = &((__half*)Cv)[
                            ((size_t)(bb * NH + hh) * DK) * S_LEN + s];
                        base[(size_t)d * S_LEN] = h0v;
                        base[(size_t)(d + 1) * S_LEN] = h1v;
                    }
                }
            }
        }
    }
}

__global__ __launch_bounds__(256, 2) void gemm_qkv_kernel(
    const __half* __restrict__ X0, const __half* __restrict__ X1,
    const __half* __restrict__ X2,
    const __half* __restrict__ W0, const __half* __restrict__ W1,
    const __half* __restrict__ W2,
    const float* __restrict__ b0, const float* __restrict__ b1,
    const float* __restrict__ b2,
    __half* __restrict__ C0, __half* __restrict__ C1, __half* __restrict__ C2) {
    extern __shared__ char smem[];
    const int z = blockIdx.z;
    if (z == 0)
        gemm_body<1>(X0, W0, b0, C0, smem, blockIdx.y * 128, blockIdx.x * 128, QSCALE_F);
    else if (z == 1)
        gemm_body<1>(X1, W1, b1, C1, smem, blockIdx.y * 128, blockIdx.x * 128, 1.0f);
    else
        gemm_body<2>(X2, W2, b2, C2, smem, blockIdx.y * 128, blockIdx.x * 128, 1.0f);
}

__global__ __launch_bounds__(256, 2) void gemm_out_kernel(
    const __half* __restrict__ X, const __half* __restrict__ W,
    const float* __restrict__ bias, float* __restrict__ C) {
    extern __shared__ char smem[];
    gemm_body<0>(X, W, bias, C, smem, blockIdx.y * 128, blockIdx.x * 128, 1.0f);
}

// ───────────── Flash attention, fp16 mma.sync ─────────────
// CTA: 64 q-rows x (head, batch), 4 warps x 16-row strips, 128 threads.
// Q/K fp16 [.,s,d]; V fp16 TRANSPOSED [.,d,s] -> all b-frags contiguous half2.
// Q smem aliased with per-warp P strips (fp16). 45 KB smem -> 4 CTAs/SM.
#define LDH 72                     // halves per row (stride 36 words: conflict-free)
#define FA_K_H (64 * LDH)
#define FA_V_H (64 * LDH)
#define FA_QP_H (64 * LDH)
#define FA_SMEM ((2 * FA_K_H + 2 * FA_V_H + FA_QP_H) * 2)

__global__ __launch_bounds__(128, 4) void flash_mma_kernel(
    const __half* __restrict__ Q, const __half* __restrict__ K,
    const __half* __restrict__ Vt, __half* __restrict__ O) {
    extern __shared__ __half smh[];
    __half* Ks = smh;
    __half* Vs = Ks + 2 * FA_K_H;
    __half* QPs = Vs + 2 * FA_V_H;

    const int qt = (int)gridDim.x - 1 - (int)blockIdx.x;   // longest first
    const int h = blockIdx.y, b = blockIdx.z;
    const int q0 = qt * 64;
    const size_t base = (size_t)((b * NH + h) * S_LEN) * DK;
    const __half* qb = Q + base + (size_t)q0 * DK;
    const __half* kb = K + base;
    const __half* vtb = Vt + (size_t)((b * NH + h) * DK) * S_LEN;

    const int t = threadIdx.x;
    const int lane = t & 31, warp = t >> 5;
    const int lr = lane >> 2, lc = lane & 3;

    const uint32_t uK = smem_to_u32(Ks);
    const uint32_t uV = smem_to_u32(Vs);
    const uint32_t uQ = smem_to_u32(QPs);

    // Q tile: 64 rows x 8 chunks = 512 chunks
#pragma unroll
    for (int i = 0; i < 4; i++) {
        int j = i * 128 + t;
        int r = j >> 3, c8 = j & 7;
        cp_async16(uQ + (uint32_t)(r * LDH + c8 * 8) * 2, qb + r * DK + c8 * 8);
    }

    auto load_kv = [&](int st, int kt) {
        int k0 = kt * 64;
#pragma unroll
        for (int i = 0; i < 8; i++) {
            int j = i * 128 + t;               // 0..1023
            int mat = j >> 9;                  // 0 = K, 1 = Vt
            int idx = j & 511;
            int r = idx >> 3, c8 = idx & 7;
            if (mat == 0)
                cp_async16(uK + (uint32_t)(st * FA_K_H + r * LDH + c8 * 8) * 2,
                           kb + (size_t)(k0 + r) * DK + c8 * 8);
            else
                cp_async16(uV + (uint32_t)(st * FA_V_H + r * LDH + c8 * 8) * 2,
                           vtb + (size_t)r * S_LEN + k0 + c8 * 8);
        }
        CP_ASYNC_COMMIT();
    };

    load_kv(0, 0);

    uint32_t qa[4][4];
    float o[8][4] = {};
    float mA = -1e30f, mB = -1e30f, lA = 0.f, lB = 0.f;
    __half* Pw = QPs + warp * 16 * LDH;
    const int rowA = warp * 16 + lr;

    const int last = qt;
    for (int kt = 0; kt <= last; kt++) {
        const int st = kt & 1;
        if (kt < last) { load_kv(st ^ 1, kt + 1); CP_ASYNC_WAIT(1); }
        else           { CP_ASYNC_WAIT(0); }
        __syncthreads();

        if (kt == 0) {
            // Q a-fragments (pre-scaled fp16). Warp reads only its own strip,
            // which it then owns as its P strip.
#pragma unroll
            for (int kc = 0; kc < 4; kc++) {
                int c = kc * 16 + 2 * lc;
                qa[kc][0] = *(const uint32_t*)&QPs[rowA * LDH + c];
                qa[kc][1] = *(const uint32_t*)&QPs[(rowA + 8) * LDH + c];
                qa[kc][2] = *(const uint32_t*)&QPs[rowA * LDH + c + 8];
                qa[kc][3] = *(const uint32_t*)&QPs[(rowA + 8) * LDH + c + 8];
            }
            __syncwarp();
        }

        const __half* Kst = Ks + st * FA_K_H;
        const __half* Vst = Vs + st * FA_V_H;

        // S = Q K^T, 16x64 strip per warp (4 kc x 8 nt fp16 k16 mma)
        float s[8][4] = {};
#pragma unroll
        for (int kc = 0; kc < 4; kc++) {
            const int c = kc * 16 + 2 * lc;
#pragma unroll
            for (int nt = 0; nt < 8; nt++) {
                uint32_t bf[2];
                const __half* kp = &Kst[(nt * 8 + lr) * LDH + c];
                bf[0] = *(const uint32_t*)kp;
                bf[1] = *(const uint32_t*)(kp + 8);
                mma_f16(s[nt], qa[kc], bf);
            }
        }

        // Causal mask (diagonal tile only)
        const int gA = q0 + rowA, gB = gA + 8;
        if (kt == last) {
            const int j0b = kt * 64;
#pragma unroll
            for (int nt = 0; nt < 8; nt++) {
                int j0 = j0b + nt * 8 + 2 * lc;
                if (j0 > gA)     s[nt][0] = -1e10f;
                if (j0 + 1 > gA) s[nt][1] = -1e10f;
                if (j0 > gB)     s[nt][2] = -1e10f;
                if (j0 + 1 > gB) s[nt][3] = -1e10f;
            }
        }

        // Online softmax in log2 domain (quad reduce via shfl.xor 1,2)
        float tmA = -1e30f, tmB = -1e30f;
#pragma unroll
        for (int nt = 0; nt < 8; nt++) {
            tmA = fmaxf(tmA, fmaxf(s[nt][0], s[nt][1]));
            tmB = fmaxf(tmB, fmaxf(s[nt][2], s[nt][3]));
        }
        tmA = fmaxf(tmA, __shfl_xor_sync(0xffffffff, tmA, 1));
        tmA = fmaxf(tmA, __shfl_xor_sync(0xffffffff, tmA, 2));
        tmB = fmaxf(tmB, __shfl_xor_sync(0xffffffff, tmB, 1));
        tmB = fmaxf(tmB, __shfl_xor_sync(0xffffffff, tmB, 2));
        float mnA = fmaxf(mA, tmA), mnB = fmaxf(mB, tmB);
        float cA = fast_exp2(mA - mnA), cB = fast_exp2(mB - mnB);
        float sumA = 0.f, sumB = 0.f;
#pragma unroll
        for (int nt = 0; nt < 8; nt++) {
            float p0 = fast_exp2(s[nt][0] - mnA);
            float p1 = fast_exp2(s[nt][1] - mnA);
            float p2 = fast_exp2(s[nt][2] - mnB);
            float p3 = fast_exp2(s[nt][3] - mnB);
            sumA += p0 + p1; sumB += p2 + p3;
            *(__half2*)&Pw[lr * LDH + nt * 8 + 2 * lc] = __floats2half2_rn(p0, p1);
            *(__half2*)&Pw[(lr + 8) * LDH + nt * 8 + 2 * lc] = __floats2half2_rn(p2, p3);
        }
        sumA += __shfl_xor_sync(0xffffffff, sumA, 1);
        sumA += __shfl_xor_sync(0xffffffff, sumA, 2);
        sumB += __shfl_xor_sync(0xffffffff, sumB, 1);
        sumB += __shfl_xor_sync(0xffffffff, sumB, 2);
        lA = lA * cA + sumA; lB = lB * cB + sumB;
        mA = mnA; mB = mnB;
#pragma unroll
        for (int nt = 0; nt < 8; nt++) {
            o[nt][0] *= cA; o[nt][1] *= cA;
            o[nt][2] *= cB; o[nt][3] *= cB;
        }
        __syncwarp();

        // O += P V  (P fp16 per-warp strip; Vt fp16, d-rows)
#pragma unroll
        for (int kc = 0; kc < 4; kc++) {
            const int c = kc * 16 + 2 * lc;
            uint32_t pa[4];
            pa[0] = *(const uint32_t*)&Pw[lr * LDH + c];
            pa[1] = *(const uint32_t*)&Pw[(lr + 8) * LDH + c];
            pa[2] = *(const uint32_t*)&Pw[lr * LDH + c + 8];
            pa[3] = *(const uint32_t*)&Pw[(lr + 8) * LDH + c + 8];
#pragma unroll
            for (int nt = 0; nt < 8; nt++) {
                uint32_t bf[2];
                const __half* vp = &Vst[(nt * 8 + lr) * LDH + c];
                bf[0] = *(const uint32_t*)vp;
                bf[1] = *(const uint32_t*)(vp + 8);
                mma_f16(o[nt], pa, bf);
            }
        }
        __syncthreads();
    }

    // Epilogue: normalize, write fp16 merged-head layout [B,S,U]
    const float invA = 1.f / lA, invB = 1.f / lB;
    const int qgA = q0 + rowA;
#pragma unroll
    for (int nt = 0; nt < 8; nt++) {
        int n = h * DK + nt * 8 + 2 * lc;
        __half2* dA = (__half2*)&O[(size_t)(b * S_LEN + qgA) * NU + n];
        *dA = __floats2half2_rn(o[nt][0] * invA, o[nt][1] * invA);
        __half2* dB = (__half2*)&O[(size_t)(b * S_LEN + qgA + 8) * NU + n];
        *dB = __floats2half2_rn(o[nt][2] * invB, o[nt][3] * invB);
    }
}

extern "C" void kernel_launch(void* const* d_in, const int* in_sizes, int n_in,
                              void* d_out, int out_size) {
    const float* query = (const float*)d_in[0];
    const float* key_  = (const float*)d_in[1];
    const float* value = (const float*)d_in[2];
    // d_in[3] = mask (int32) — causal tril, handled analytically.
    const float* Wq = (const float*)d_in[4];
    const float* bq = (const float*)d_in[5];
    const float* Wk = (const float*)d_in[6];
    const float* bk = (const float*)d_in[7];
    const float* Wv = (const float*)d_in[8];
    const float* bv = (const float*)d_in[9];
    const float* Wo = (const float*)d_in[10];
    const float* bo = (const float*)d_in[11];

    __half *pq, *pk, *pv, *pa, *pxq, *pxk, *pxv, *pwq, *pwk, *pwv, *pwo;
    cudaGetSymbolAddress((void**)&pq, g_q);
    cudaGetSymbolAddress((void**)&pk, g_k);
    cudaGetSymbolAddress((void**)&pv, g_v);
    cudaGetSymbolAddress((void**)&pa, g_attn);
    cudaGetSymbolAddress((void**)&pxq, g_xq);
    cudaGetSymbolAddress((void**)&pxk, g_xk);
    cudaGetSymbolAddress((void**)&pxv, g_xv);
    cudaGetSymbolAddress((void**)&pwq, g_wq);
    cudaGetSymbolAddress((void**)&pwk, g_wk);
    cudaGetSymbolAddress((void**)&pwv, g_wv);
    cudaGetSymbolAddress((void**)&pwo, g_wo);

    cudaFuncSetAttribute(gemm_qkv_kernel,
                         cudaFuncAttributeMaxDynamicSharedMemorySize, GEMM_SMEM);
    cudaFuncSetAttribute(gemm_out_kernel,
                         cudaFuncAttributeMaxDynamicSharedMemorySize, GEMM_SMEM);
    cudaFuncSetAttribute(flash_mma_kernel,
                         cudaFuncAttributeMaxDynamicSharedMemorySize, FA_SMEM);

    preround_kernel<<<dim3(1024, 1, 7), 256>>>(
        query, key_, value, Wq, Wk, Wv, Wo,
        pxq, pxk, pxv, pwq, pwk, pwv, pwo);

    gemm_qkv_kernel<<<dim3(NU / 128, MROWS / 128, 3), 256, GEMM_SMEM>>>(
        pxq, pxk, pxv, pwq, pwk, pwv, bq, bk, bv, pq, pk, pv);

    flash_mma_kernel<<<dim3(S_LEN / 64, NH, BATCH), 128, FA_SMEM>>>(pq, pk, pv, pa);

    gemm_out_kernel<<<dim3(NU / 128, MROWS / 128), 256, GEMM_SMEM>>>(
        pa, pwo, bo, (float*)d_out);
}